// round 1
// baseline (speedup 1.0000x reference)
#include <cuda_runtime.h>
#include <cuda_bf16.h>

// ObjCondensationLoss — N hits, K clusters, D coords.
//
// Inputs (metadata order): x (N*D f32), beta (N f32), y (N i32),
//                          K (i32 scalar), S_b (f32 scalar), q_min (f32 scalar)
// Output: scalar f32 loss.

#define KMAX 1024
#define TB   256

__device__ unsigned int       g_beta_bits[KMAX];   // max beta per cluster (float bits, beta>0)
__device__ unsigned long long g_qpack[KMAX];       // (q_bits<<32) | (0xFFFFFFFF - idx)
__device__ float4             g_xaq[KMAX];         // {x_a.x, x_a.y, x_a.z, q_ak}
__device__ double             g_sum_bg;            // sum beta over background
__device__ unsigned long long g_cnt_bg;            // N_b
__device__ double             g_sum_perhit;        // sum(per_hit * q_i)

__device__ __forceinline__ float blockReduceSum(float v) {
    __shared__ float warpsum[32];
    int lane = threadIdx.x & 31;
    int wid  = threadIdx.x >> 5;
    #pragma unroll
    for (int o = 16; o > 0; o >>= 1) v += __shfl_down_sync(0xffffffffu, v, o);
    if (lane == 0) warpsum[wid] = v;
    __syncthreads();
    int nwarps = (blockDim.x + 31) >> 5;
    v = (threadIdx.x < nwarps) ? warpsum[threadIdx.x] : 0.0f;
    if (wid == 0) {
        #pragma unroll
        for (int o = 16; o > 0; o >>= 1) v += __shfl_down_sync(0xffffffffu, v, o);
    }
    return v;  // valid in thread 0
}

__global__ void k_init() {
    int k = blockIdx.x * blockDim.x + threadIdx.x;
    if (k < KMAX) {
        g_beta_bits[k] = 0u;
        g_qpack[k]     = 0ull;
        g_xaq[k]       = make_float4(0.f, 0.f, 0.f, 0.f);
    }
    if (k == 0) { g_sum_bg = 0.0; g_cnt_bg = 0ull; g_sum_perhit = 0.0; }
}

__global__ void k_scan(const float* __restrict__ beta, const int* __restrict__ y,
                       const float* __restrict__ qminp, int N) {
    int i = blockIdx.x * blockDim.x + threadIdx.x;
    if (i >= N) return;
    float qmin = qminp ? __ldg(qminp) : 0.5f;
    int   yi = y[i];
    float b  = beta[i];
    if (yi >= 0) {
        atomicMax(&g_beta_bits[yi], __float_as_uint(b));
        float a = atanhf(b);
        float q = fmaf(a, a, qmin);                      // q > 0
        unsigned long long p =
            ((unsigned long long)__float_as_uint(q) << 32) |
            (unsigned long long)(0xFFFFFFFFu - (unsigned)i);   // tie -> min index
        atomicMax(&g_qpack[yi], p);
    } else {
        atomicAdd(&g_sum_bg, (double)b);
        atomicAdd(&g_cnt_bg, 1ull);
    }
}

__global__ void k_gather(const float* __restrict__ x, const int* __restrict__ Kp, int D) {
    int k = blockIdx.x * blockDim.x + threadIdx.x;
    int K = Kp ? __ldg(Kp) : 256;
    if (k >= K) return;
    unsigned long long p = g_qpack[k];
    float    q   = 0.0f;
    unsigned idx = 0u;
    if (p != 0ull) {
        q   = __uint_as_float((unsigned)(p >> 32));
        idx = 0xFFFFFFFFu - (unsigned)p;
    }
    const float* xp = x + (size_t)idx * (size_t)D;
    float4 v;
    v.x = xp[0];
    v.y = (D > 1) ? xp[1] : 0.0f;
    v.z = (D > 2) ? xp[2] : 0.0f;
    v.w = q;
    g_xaq[k] = v;
}

// Main potential kernel (D == 3 fast path). 2 hits per thread.
__global__ void k_main3(const float* __restrict__ x, const float* __restrict__ beta,
                        const int* __restrict__ y, const int* __restrict__ Kp,
                        const float* __restrict__ qminp, int N) {
    __shared__ float4 s_xaq[KMAX];
    int   K    = Kp ? __ldg(Kp) : 256;
    float qmin = qminp ? __ldg(qminp) : 0.5f;
    for (int k = threadIdx.x; k < K; k += blockDim.x) s_xaq[k] = g_xaq[k];
    __syncthreads();

    int i0 = (blockIdx.x * blockDim.x + threadIdx.x) * 2;
    int i1 = i0 + 1;

    float x00 = 0.f, x01 = 0.f, x02 = 0.f;
    float x10 = 0.f, x11 = 0.f, x12 = 0.f;
    float q0 = 0.f, q1 = 0.f;
    int   y0 = -2, y1 = -2;

    if (i0 < N) {
        x00 = x[(size_t)i0 * 3 + 0];
        x01 = x[(size_t)i0 * 3 + 1];
        x02 = x[(size_t)i0 * 3 + 2];
        y0  = y[i0];
        float b = beta[i0], a = atanhf(b);
        q0 = fmaf(a, a, qmin);
    }
    if (i1 < N) {
        x10 = x[(size_t)i1 * 3 + 0];
        x11 = x[(size_t)i1 * 3 + 1];
        x12 = x[(size_t)i1 * 3 + 2];
        y1  = y[i1];
        float b = beta[i1], a = atanhf(b);
        q1 = fmaf(a, a, qmin);
    }

    float acc0 = 0.f, acc1 = 0.f;
    #pragma unroll 4
    for (int k = 0; k < K; ++k) {
        float4 c = s_xaq[k];
        float dx = x00 - c.x, dy = x01 - c.y, dz = x02 - c.z;
        float d0 = fmaf(dx, dx, fmaf(dy, dy, dz * dz));
        float t0 = (k == y0) ? d0 : fmaxf(1.0f - d0, 0.0f);
        acc0 = fmaf(t0, c.w, acc0);

        dx = x10 - c.x; dy = x11 - c.y; dz = x12 - c.z;
        float d1 = fmaf(dx, dx, fmaf(dy, dy, dz * dz));
        float t1 = (k == y1) ? d1 : fmaxf(1.0f - d1, 0.0f);
        acc1 = fmaf(t1, c.w, acc1);
    }

    float val = acc0 * q0 + acc1 * q1;  // q==0 for out-of-range lanes
    float bs  = blockReduceSum(val);
    if (threadIdx.x == 0) atomicAdd(&g_sum_perhit, (double)bs);
}

// Generic-D fallback (shared layout: q[K] then xa[K*D])
__global__ void k_mainD(const float* __restrict__ x, const float* __restrict__ beta,
                        const int* __restrict__ y, const int* __restrict__ Kp,
                        const float* __restrict__ qminp,
                        const float* __restrict__ xa_src_x, int N, int D) {
    extern __shared__ float sm[];
    int   K    = Kp ? __ldg(Kp) : 256;
    float qmin = qminp ? __ldg(qminp) : 0.5f;
    float* s_q  = sm;          // K
    float* s_xa = sm + K;      // K*D
    for (int k = threadIdx.x; k < K; k += blockDim.x) {
        unsigned long long p = g_qpack[k];
        float    q   = 0.0f;
        unsigned idx = 0u;
        if (p != 0ull) { q = __uint_as_float((unsigned)(p >> 32)); idx = 0xFFFFFFFFu - (unsigned)p; }
        s_q[k] = q;
        for (int d = 0; d < D; ++d) s_xa[k * D + d] = xa_src_x[(size_t)idx * D + d];
    }
    __syncthreads();

    int i = blockIdx.x * blockDim.x + threadIdx.x;
    float val = 0.0f;
    if (i < N) {
        int   yi = y[i];
        float b = beta[i], a = atanhf(b);
        float qi = fmaf(a, a, qmin);
        float acc = 0.0f;
        for (int k = 0; k < K; ++k) {
            float d = 0.0f;
            for (int dd = 0; dd < D; ++dd) {
                float t = x[(size_t)i * D + dd] - s_xa[k * D + dd];
                d = fmaf(t, t, d);
            }
            float t = (k == yi) ? d : fmaxf(1.0f - d, 0.0f);
            acc = fmaf(t, s_q[k], acc);
        }
        val = acc * qi;
    }
    float bs = blockReduceSum(val);
    if (threadIdx.x == 0) atomicAdd(&g_sum_perhit, (double)bs);
}

__global__ void k_final(const int* __restrict__ Kp, const float* __restrict__ Sbp,
                        float* __restrict__ out, int N) {
    int   K  = Kp ? __ldg(Kp) : 256;
    float Sb = Sbp ? __ldg(Sbp) : 1.0f;
    float local = 0.0f;
    for (int k = threadIdx.x; k < K; k += blockDim.x)
        local += 1.0f - __uint_as_float(g_beta_bits[k]);
    float s = blockReduceSum(local);
    if (threadIdx.x == 0) {
        double Nb = (double)g_cnt_bg;
        if (Nb < 1.0) Nb = 1.0;
        double L = (double)s / (double)K
                 + ((double)Sb / Nb) * g_sum_bg
                 + g_sum_perhit / (double)N;
        out[0] = (float)L;
    }
}

extern "C" void kernel_launch(void* const* d_in, const int* in_sizes, int n_in,
                              void* d_out, int out_size) {
    const float* x    = (const float*)d_in[0];
    const float* beta = (const float*)d_in[1];
    const int*   y    = (const int*)d_in[2];
    const int*   Kp   = (n_in > 3) ? (const int*)d_in[3]   : nullptr;
    const float* Sbp  = (n_in > 4) ? (const float*)d_in[4] : nullptr;
    const float* qmp  = (n_in > 5) ? (const float*)d_in[5] : nullptr;

    int N = in_sizes[1];
    int D = (N > 0) ? (in_sizes[0] / N) : 3;
    float* out = (float*)d_out;

    k_init<<<(KMAX + TB - 1) / TB, TB>>>();
    k_scan<<<(N + TB - 1) / TB, TB>>>(beta, y, qmp, N);
    k_gather<<<(KMAX + TB - 1) / TB, TB>>>(x, Kp, D);

    if (D == 3) {
        int pairs  = (N + 1) / 2;
        int blocks = (pairs + TB - 1) / TB;
        k_main3<<<blocks, TB>>>(x, beta, y, Kp, qmp, N);
    } else {
        int blocks = (N + TB - 1) / TB;
        size_t smem = (size_t)KMAX * (1 + (size_t)D) * sizeof(float);
        k_mainD<<<blocks, TB, smem>>>(x, beta, y, Kp, qmp, x, N, D);
    }

    k_final<<<1, TB>>>(Kp, Sbp, out, N);
    (void)out_size;
}

// round 2
// speedup vs baseline: 1.8245x; 1.8245x over previous
#include <cuda_runtime.h>
#include <cuda_bf16.h>

// ObjCondensationLoss — N hits, K clusters, D=3 coords (generic-D fallback kept).
// Inputs: x (N*3 f32), beta (N f32), y (N i32), K (i32), S_b (f32), q_min (f32)
// Output: scalar f32 loss.

#define KMAX 1024
#define TB_SCAN 256
#define TB_MAIN 352
#define NBLK    148

typedef unsigned long long ull;

// pack = (beta_bits << 32) | (0xFFFFFFFF - i). beta>0 so float-bit order == value
// order; atanh monotone => argmax(q) == argmax(beta); tie -> smallest index.
__device__ ull    g_pack[KMAX];
__device__ double g_sum_bg;       // sum beta over background hits
__device__ double g_cnt_bg;      // N_b
__device__ double g_sum_perhit;  // sum(per_hit * q_i)
__device__ unsigned g_done;

// ---------- f32x2 packed helpers ----------
__device__ __forceinline__ ull pack2(float lo, float hi) {
    ull r; asm("mov.b64 %0, {%1, %2};" : "=l"(r) : "f"(lo), "f"(hi)); return r;
}
__device__ __forceinline__ void unpack2(ull v, float& lo, float& hi) {
    asm("mov.b64 {%0, %1}, %2;" : "=f"(lo), "=f"(hi) : "l"(v));
}
__device__ __forceinline__ ull add2(ull a, ull b) {
    ull d; asm("add.rn.f32x2 %0, %1, %2;" : "=l"(d) : "l"(a), "l"(b)); return d;
}
__device__ __forceinline__ ull fma2(ull a, ull b, ull c) {
    ull d; asm("fma.rn.f32x2 %0, %1, %2, %3;" : "=l"(d) : "l"(a), "l"(b), "l"(c)); return d;
}

__device__ __forceinline__ float blockReduceSum(float v) {
    __shared__ float warpsum[32];
    int lane = threadIdx.x & 31;
    int wid  = threadIdx.x >> 5;
    #pragma unroll
    for (int o = 16; o > 0; o >>= 1) v += __shfl_down_sync(0xffffffffu, v, o);
    if (lane == 0) warpsum[wid] = v;
    __syncthreads();
    int nwarps = (blockDim.x + 31) >> 5;
    v = ((int)threadIdx.x < nwarps) ? warpsum[threadIdx.x] : 0.0f;
    if (wid == 0) {
        #pragma unroll
        for (int o = 16; o > 0; o >>= 1) v += __shfl_down_sync(0xffffffffu, v, o);
    }
    return v;  // valid in thread 0
}

__device__ __forceinline__ float2 blockReduceSum2(float a, float b) {
    __shared__ float2 ws[32];
    int lane = threadIdx.x & 31;
    int wid  = threadIdx.x >> 5;
    #pragma unroll
    for (int o = 16; o > 0; o >>= 1) {
        a += __shfl_down_sync(0xffffffffu, a, o);
        b += __shfl_down_sync(0xffffffffu, b, o);
    }
    if (lane == 0) ws[wid] = make_float2(a, b);
    __syncthreads();
    int nwarps = (blockDim.x + 31) >> 5;
    a = ((int)threadIdx.x < nwarps) ? ws[threadIdx.x].x : 0.0f;
    b = ((int)threadIdx.x < nwarps) ? ws[threadIdx.x].y : 0.0f;
    if (wid == 0) {
        #pragma unroll
        for (int o = 16; o > 0; o >>= 1) {
            a += __shfl_down_sync(0xffffffffu, a, o);
            b += __shfl_down_sync(0xffffffffu, b, o);
        }
    }
    return make_float2(a, b);  // valid in thread 0
}

__global__ void k_init() {
    int k = blockIdx.x * blockDim.x + threadIdx.x;
    if (k < KMAX) g_pack[k] = 0ull;
    if (k == 0) { g_sum_bg = 0.0; g_cnt_bg = 0.0; g_sum_perhit = 0.0; g_done = 0u; }
}

// Scan: shared-memory aggregated packed atomicMax + background sums.
__global__ void k_scan(const float* __restrict__ beta, const int* __restrict__ y, int N) {
    __shared__ ull sh[KMAX];
    for (int k = threadIdx.x; k < KMAX; k += blockDim.x) sh[k] = 0ull;
    __syncthreads();

    float bg = 0.0f, cnt = 0.0f;
    int stride = gridDim.x * blockDim.x;
    for (int i = blockIdx.x * blockDim.x + threadIdx.x; i < N; i += stride) {
        int   yi = y[i];
        float b  = beta[i];
        if (yi >= 0) {
            ull p = ((ull)__float_as_uint(b) << 32) |
                    (ull)(0xFFFFFFFFu - (unsigned)i);
            atomicMax(&sh[yi], p);
        } else {
            bg += b; cnt += 1.0f;
        }
    }
    __syncthreads();
    for (int k = threadIdx.x; k < KMAX; k += blockDim.x) {
        ull p = sh[k];
        if (p) atomicMax(&g_pack[k], p);
    }
    float2 r = blockReduceSum2(bg, cnt);
    if (threadIdx.x == 0) {
        if (r.x != 0.0f) atomicAdd(&g_sum_bg, (double)r.x);
        if (r.y != 0.0f) atomicAdd(&g_cnt_bg, (double)r.y);
    }
}

// Main D==3 kernel: fused gather (table build), packed 2-hit inner loop,
// fused finalize via last-block counter.
__global__ void __launch_bounds__(TB_MAIN)
k_main3(const float* __restrict__ x, const float* __restrict__ beta,
        const int* __restrict__ y, const int* __restrict__ Kp,
        const float* __restrict__ Sbp, const float* __restrict__ qminp,
        float* __restrict__ out, int N) {
    // table row k: s_tab[2k] = {(-xa,-xa),(-ya,-ya)}  s_tab[2k+1] = {(-za,-za),(q,q)}
    __shared__ ulonglong2 s_tab[2 * KMAX];
    int   K    = Kp   ? __ldg(Kp)   : 256;
    float qmin = qminp ? __ldg(qminp) : 0.5f;

    for (int k = threadIdx.x; k < K; k += blockDim.x) {
        ull p = g_pack[k];
        float q = 0.0f;
        unsigned idx = 0u;
        if (p != 0ull) {
            float b = __uint_as_float((unsigned)(p >> 32));
            float a = atanhf(b);
            q = fmaf(a, a, qmin);
            idx = 0xFFFFFFFFu - (unsigned)p;
        }
        float nx = -x[(size_t)idx * 3 + 0];
        float ny = -x[(size_t)idx * 3 + 1];
        float nz = -x[(size_t)idx * 3 + 2];
        s_tab[2 * k]     = make_ulonglong2(pack2(nx, nx), pack2(ny, ny));
        s_tab[2 * k + 1] = make_ulonglong2(pack2(nz, nz), pack2(q, q));
    }
    __syncthreads();

    int npairs = (N + 1) >> 1;
    int stride = gridDim.x * blockDim.x;
    float val = 0.0f;

    for (int pi = blockIdx.x * blockDim.x + threadIdx.x; pi < npairs; pi += stride) {
        int i0 = 2 * pi;
        int i1 = i0 + 1;
        bool has1 = (i1 < N);
        int j1 = has1 ? i1 : i0;

        float a0x = x[(size_t)i0 * 3 + 0];
        float a0y = x[(size_t)i0 * 3 + 1];
        float a0z = x[(size_t)i0 * 3 + 2];
        float a1x = x[(size_t)j1 * 3 + 0];
        float a1y = x[(size_t)j1 * 3 + 1];
        float a1z = x[(size_t)j1 * 3 + 2];
        int y0 = y[i0];
        int y1 = has1 ? y[i1] : -1;
        float b0 = beta[i0], at0 = atanhf(b0);
        float q0 = fmaf(at0, at0, qmin);
        float q1 = 0.0f;
        if (has1) { float b1 = beta[i1], at1 = atanhf(b1); q1 = fmaf(at1, at1, qmin); }

        ull X = pack2(a0x, a1x), Y = pack2(a0y, a1y), Z = pack2(a0z, a1z);
        const ull NEG1 = 0xBF800000BF800000ULL;  // {-1.0f, -1.0f}

        float s0 = 0.0f, s1 = 0.0f;
        #pragma unroll 4
        for (int k = 0; k < K; ++k) {
            ulonglong2 t0 = s_tab[2 * k];
            ulonglong2 t1 = s_tab[2 * k + 1];
            ull dx = add2(X, t0.x);
            ull dy = add2(Y, t0.y);
            ull dz = add2(Z, t1.x);
            // m = d - 1  (both lanes)
            ull m = fma2(dz, dz, fma2(dy, dy, fma2(dx, dx, NEG1)));
            float m0, m1, qk0, qk1;
            unpack2(m, m0, m1);
            unpack2(t1.y, qk0, qk1);
            float r0 = fmaxf(-m0, 0.0f);   // max(1-d, 0)
            float r1 = fmaxf(-m1, 0.0f);
            s0 = fmaf(r0, qk0, s0);
            s1 = fmaf(r1, qk1, s1);
        }
        // member corrections: replace repulsive with attractive for own cluster
        if ((unsigned)y0 < (unsigned)K) {
            ulonglong2 t0 = s_tab[2 * y0], t1 = s_tab[2 * y0 + 1];
            float nx, ny, nz, qk, hh;
            unpack2(t0.x, nx, hh); unpack2(t0.y, ny, hh);
            unpack2(t1.x, nz, hh); unpack2(t1.y, qk, hh);
            float dx = a0x + nx, dy = a0y + ny, dz = a0z + nz;
            float d = fmaf(dx, dx, fmaf(dy, dy, dz * dz));
            s0 += (d - fmaxf(1.0f - d, 0.0f)) * qk;
        }
        if ((unsigned)y1 < (unsigned)K) {
            ulonglong2 t0 = s_tab[2 * y1], t1 = s_tab[2 * y1 + 1];
            float nx, ny, nz, qk, hh;
            unpack2(t0.x, nx, hh); unpack2(t0.y, ny, hh);
            unpack2(t1.x, nz, hh); unpack2(t1.y, qk, hh);
            float dx = a1x + nx, dy = a1y + ny, dz = a1z + nz;
            float d = fmaf(dx, dx, fmaf(dy, dy, dz * dz));
            s1 += (d - fmaxf(1.0f - d, 0.0f)) * qk;
        }
        val += s0 * q0 + s1 * q1;
    }

    float bs = blockReduceSum(val);
    if (threadIdx.x == 0) {
        atomicAdd(&g_sum_perhit, (double)bs);
        __threadfence();
        unsigned old = atomicAdd(&g_done, 1u);
        if (old == gridDim.x - 1) {
            // finalize (all blocks' atomics are visible after fence+counter)
            float Sb = Sbp ? __ldg(Sbp) : 1.0f;
            float sbeta = 0.0f;
            for (int k = 0; k < K; ++k) {
                ull p = g_pack[k];
                sbeta += 1.0f - __uint_as_float((unsigned)(p >> 32));
            }
            double sum_bg  = atomicAdd(&g_sum_bg, 0.0);
            double cnt_bg  = atomicAdd(&g_cnt_bg, 0.0);
            double sum_ph  = atomicAdd(&g_sum_perhit, 0.0);
            if (cnt_bg < 1.0) cnt_bg = 1.0;
            double L = (double)sbeta / (double)K
                     + ((double)Sb / cnt_bg) * sum_bg
                     + sum_ph / (double)N;
            out[0] = (float)L;
        }
    }
}

// ---------------- generic-D fallback ----------------
__global__ void k_mainD(const float* __restrict__ x, const float* __restrict__ beta,
                        const int* __restrict__ y, const int* __restrict__ Kp,
                        const float* __restrict__ qminp, int N, int D) {
    extern __shared__ float sm[];
    int   K    = Kp   ? __ldg(Kp)   : 256;
    float qmin = qminp ? __ldg(qminp) : 0.5f;
    float* s_q  = sm;
    float* s_xa = sm + K;
    for (int k = threadIdx.x; k < K; k += blockDim.x) {
        ull p = g_pack[k];
        float q = 0.0f; unsigned idx = 0u;
        if (p != 0ull) {
            float b = __uint_as_float((unsigned)(p >> 32));
            float a = atanhf(b);
            q = fmaf(a, a, qmin);
            idx = 0xFFFFFFFFu - (unsigned)p;
        }
        s_q[k] = q;
        for (int d = 0; d < D; ++d) s_xa[k * D + d] = x[(size_t)idx * D + d];
    }
    __syncthreads();

    int i = blockIdx.x * blockDim.x + threadIdx.x;
    float val = 0.0f;
    if (i < N) {
        int   yi = y[i];
        float b = beta[i], a = atanhf(b);
        float qi = fmaf(a, a, qmin);
        float acc = 0.0f;
        for (int k = 0; k < K; ++k) {
            float d = 0.0f;
            for (int dd = 0; dd < D; ++dd) {
                float t = x[(size_t)i * D + dd] - s_xa[k * D + dd];
                d = fmaf(t, t, d);
            }
            float t = (k == yi) ? d : fmaxf(1.0f - d, 0.0f);
            acc = fmaf(t, s_q[k], acc);
        }
        val = acc * qi;
    }
    float bs = blockReduceSum(val);
    if (threadIdx.x == 0) atomicAdd(&g_sum_perhit, (double)bs);
}

__global__ void k_final(const int* __restrict__ Kp, const float* __restrict__ Sbp,
                        float* __restrict__ out, int N) {
    int   K  = Kp  ? __ldg(Kp)  : 256;
    float Sb = Sbp ? __ldg(Sbp) : 1.0f;
    float local = 0.0f;
    for (int k = threadIdx.x; k < K; k += blockDim.x) {
        ull p = g_pack[k];
        local += 1.0f - __uint_as_float((unsigned)(p >> 32));
    }
    float s = blockReduceSum(local);
    if (threadIdx.x == 0) {
        double Nb = g_cnt_bg;
        if (Nb < 1.0) Nb = 1.0;
        double L = (double)s / (double)K
                 + ((double)Sb / Nb) * g_sum_bg
                 + g_sum_perhit / (double)N;
        out[0] = (float)L;
    }
}

extern "C" void kernel_launch(void* const* d_in, const int* in_sizes, int n_in,
                              void* d_out, int out_size) {
    const float* x    = (const float*)d_in[0];
    const float* beta = (const float*)d_in[1];
    const int*   y    = (const int*)d_in[2];
    const int*   Kp   = (n_in > 3) ? (const int*)d_in[3]   : nullptr;
    const float* Sbp  = (n_in > 4) ? (const float*)d_in[4] : nullptr;
    const float* qmp  = (n_in > 5) ? (const float*)d_in[5] : nullptr;

    int N = in_sizes[1];
    int D = (N > 0) ? (in_sizes[0] / N) : 3;
    float* out = (float*)d_out;

    k_init<<<(KMAX + 255) / 256, 256>>>();
    k_scan<<<NBLK, TB_SCAN>>>(beta, y, N);

    if (D == 3) {
        k_main3<<<NBLK, TB_MAIN>>>(x, beta, y, Kp, Sbp, qmp, out, N);
    } else {
        int blocks = (N + TB_SCAN - 1) / TB_SCAN;
        size_t smem = (size_t)KMAX * (1 + (size_t)D) * sizeof(float);
        k_mainD<<<blocks, TB_SCAN, smem>>>(x, beta, y, Kp, qmp, N, D);
        k_final<<<1, 256>>>(Kp, Sbp, out, N);
    }
    (void)out_size;
}

// round 4
// speedup vs baseline: 2.2668x; 1.2424x over previous
#include <cuda_runtime.h>
#include <cuda_bf16.h>

// ObjCondensationLoss — single fused persistent kernel (D==3 fast path).
// Inputs: x (N*3 f32), beta (N f32), y (N i32), K (i32), S_b (f32), q_min (f32)
// Output: scalar f32 loss.
//
// Invariant: all __device__ globals below are ZERO at kernel entry (zero at
// module load; the finalizing block restores zeros before exit each call).

#define KMAX    1024
#define TB_MAIN 352
#define NBLK    148

typedef unsigned long long ull;

// pack = (beta_bits << 32) | (0xFFFFFFFF - i). beta>0 => float-bit order == value
// order; atanh monotone => argmax(q) == argmax(beta); tie -> smallest index.
__device__ ull      g_pack[KMAX];
__device__ double   g_sum_bg;      // sum beta over background hits
__device__ double   g_cnt_bg;      // N_b
__device__ double   g_sum_perhit;  // sum(per_hit * q_i)
__device__ unsigned g_bar_cnt;     // grid barrier counter
__device__ unsigned g_done;        // finalize counter

// ---------- f32x2 packed helpers ----------
__device__ __forceinline__ ull pack2(float lo, float hi) {
    ull r; asm("mov.b64 %0, {%1, %2};" : "=l"(r) : "f"(lo), "f"(hi)); return r;
}
__device__ __forceinline__ void unpack2(ull v, float& lo, float& hi) {
    asm("mov.b64 {%0, %1}, %2;" : "=f"(lo), "=f"(hi) : "l"(v));
}
__device__ __forceinline__ ull add2(ull a, ull b) {
    ull d; asm("add.rn.f32x2 %0, %1, %2;" : "=l"(d) : "l"(a), "l"(b)); return d;
}
__device__ __forceinline__ ull fma2(ull a, ull b, ull c) {
    ull d; asm("fma.rn.f32x2 %0, %1, %2, %3;" : "=l"(d) : "l"(a), "l"(b), "l"(c)); return d;
}

__device__ __forceinline__ float blockReduceSum(float v) {
    __shared__ float warpsum[32];
    int lane = threadIdx.x & 31;
    int wid  = threadIdx.x >> 5;
    #pragma unroll
    for (int o = 16; o > 0; o >>= 1) v += __shfl_down_sync(0xffffffffu, v, o);
    if (lane == 0) warpsum[wid] = v;
    __syncthreads();
    int nwarps = (blockDim.x + 31) >> 5;
    v = ((int)threadIdx.x < nwarps) ? warpsum[threadIdx.x] : 0.0f;
    if (wid == 0) {
        #pragma unroll
        for (int o = 16; o > 0; o >>= 1) v += __shfl_down_sync(0xffffffffu, v, o);
    }
    __syncthreads();   // protect warpsum reuse across calls
    return v;  // valid in thread 0
}

__device__ __forceinline__ float2 blockReduceSum2(float a, float b) {
    __shared__ float2 ws[32];
    int lane = threadIdx.x & 31;
    int wid  = threadIdx.x >> 5;
    #pragma unroll
    for (int o = 16; o > 0; o >>= 1) {
        a += __shfl_down_sync(0xffffffffu, a, o);
        b += __shfl_down_sync(0xffffffffu, b, o);
    }
    if (lane == 0) ws[wid] = make_float2(a, b);
    __syncthreads();
    int nwarps = (blockDim.x + 31) >> 5;
    a = ((int)threadIdx.x < nwarps) ? ws[threadIdx.x].x : 0.0f;
    b = ((int)threadIdx.x < nwarps) ? ws[threadIdx.x].y : 0.0f;
    if (wid == 0) {
        #pragma unroll
        for (int o = 16; o > 0; o >>= 1) {
            a += __shfl_down_sync(0xffffffffu, a, o);
            b += __shfl_down_sync(0xffffffffu, b, o);
        }
    }
    __syncthreads();
    return make_float2(a, b);  // valid in thread 0
}

// ================= fused persistent kernel (D == 3) =================
__global__ void __launch_bounds__(TB_MAIN)
k_fused3(const float* __restrict__ x, const float* __restrict__ beta,
         const int* __restrict__ y, const int* __restrict__ Kp,
         const float* __restrict__ Sbp, const float* __restrict__ qminp,
         float* __restrict__ out, int N) {
    // 40KB shared arena. Phase A: s_mem[0..KMAX) = pack table.
    // Phase B (after grid barrier): cxy[2*KMAX], czc[2*KMAX], q[KMAX].
    __shared__ ull s_mem[5 * KMAX];
    ull*        s_packA = s_mem;                                  // phase A
    ulonglong2* s_cxy   = reinterpret_cast<ulonglong2*>(s_mem);   // phase B [KMAX]
    ulonglong2* s_czc   = reinterpret_cast<ulonglong2*>(s_mem + 2 * KMAX);
    ull*        s_q     = s_mem + 4 * KMAX;

    int   K    = Kp    ? __ldg(Kp)    : 256;
    float qmin = qminp ? __ldg(qminp) : 0.5f;

    // ---------------- Phase A: scan ----------------
    for (int k = threadIdx.x; k < K; k += blockDim.x) s_packA[k] = 0ull;
    __syncthreads();

    float bg = 0.0f, cnt = 0.0f;
    int gstride = gridDim.x * blockDim.x;
    for (int i = blockIdx.x * blockDim.x + threadIdx.x; i < N; i += gstride) {
        int   yi = y[i];
        float b  = beta[i];
        if (yi >= 0) {
            ull p = ((ull)__float_as_uint(b) << 32) |
                    (ull)(0xFFFFFFFFu - (unsigned)i);
            atomicMax(&s_packA[yi], p);
        } else {
            bg += b; cnt += 1.0f;
        }
    }
    __syncthreads();
    for (int k = threadIdx.x; k < K; k += blockDim.x) {
        ull p = s_packA[k];
        if (p) atomicMax(&g_pack[k], p);
    }
    {
        float2 r = blockReduceSum2(bg, cnt);
        if (threadIdx.x == 0) {
            if (r.x != 0.0f) atomicAdd(&g_sum_bg, (double)r.x);
            if (r.y != 0.0f) atomicAdd(&g_cnt_bg, (double)r.y);
        }
    }
    __syncthreads();   // all uses of s_packA complete before phase B overwrite

    // ---------------- grid barrier ----------------
    if (threadIdx.x == 0) {
        __threadfence();
        atomicAdd(&g_bar_cnt, 1u);
        while (atomicAdd(&g_bar_cnt, 0u) < gridDim.x) { }
        __threadfence();
    }
    __syncthreads();

    // ---------------- Phase B: build coefficient table ----------------
    // d - 1 = cx*hx + cy*hy + cz*hz + (c3 + |h|^2),  cx = -2*xa.x,  c3 = |xa|^2 - 1.
    for (int k = threadIdx.x; k < K; k += blockDim.x) {
        ull p = __ldcg(&g_pack[k]);
        float q = 0.0f;
        unsigned idx = 0u;
        if (p != 0ull) {
            float b = __uint_as_float((unsigned)(p >> 32));
            float a = atanhf(b);
            q = fmaf(a, a, qmin);
            idx = 0xFFFFFFFFu - (unsigned)p;
        }
        float xa = x[(size_t)idx * 3 + 0];
        float ya = x[(size_t)idx * 3 + 1];
        float za = x[(size_t)idx * 3 + 2];
        float cx = -2.0f * xa, cy = -2.0f * ya, cz = -2.0f * za;
        float c3 = fmaf(xa, xa, fmaf(ya, ya, za * za)) - 1.0f;
        s_cxy[k] = make_ulonglong2(pack2(cx, cx), pack2(cy, cy));
        s_czc[k] = make_ulonglong2(pack2(cz, cz), pack2(c3, c3));
        s_q[k]   = pack2(q, q);
    }
    __syncthreads();

    // ---------------- Phase B: potential sum ----------------
    int npairs = (N + 1) >> 1;
    float val = 0.0f;

    for (int pi = blockIdx.x * blockDim.x + threadIdx.x; pi < npairs; pi += gstride) {
        int i0 = 2 * pi;
        int i1 = i0 + 1;
        bool has1 = (i1 < N);
        int  j1 = has1 ? i1 : i0;

        float h0x = x[(size_t)i0 * 3 + 0];
        float h0y = x[(size_t)i0 * 3 + 1];
        float h0z = x[(size_t)i0 * 3 + 2];
        float h1x = x[(size_t)j1 * 3 + 0];
        float h1y = x[(size_t)j1 * 3 + 1];
        float h1z = x[(size_t)j1 * 3 + 2];
        int y0 = y[i0];
        int y1 = has1 ? y[i1] : -1;
        float b0 = beta[i0], at0 = atanhf(b0);
        float q0 = fmaf(at0, at0, qmin);
        float q1 = 0.0f;
        if (has1) { float b1 = beta[i1], at1 = atanhf(b1); q1 = fmaf(at1, at1, qmin); }

        float base0 = fmaf(h0x, h0x, fmaf(h0y, h0y, h0z * h0z));
        float base1 = fmaf(h1x, h1x, fmaf(h1y, h1y, h1z * h1z));
        ull X = pack2(h0x, h1x), Y = pack2(h0y, h1y), Z = pack2(h0z, h1z);
        ull BASE = pack2(base0, base1);

        float s0 = 0.0f, s1 = 0.0f;
        #pragma unroll 4
        for (int k = 0; k < K; ++k) {
            ulonglong2 t0 = s_cxy[k];
            ulonglong2 t1 = s_czc[k];
            ull Q = s_q[k];
            // m = d - 1 (both lanes)
            ull m = fma2(t0.x, X, fma2(t0.y, Y, fma2(t1.x, Z, add2(t1.y, BASE))));
            float m0, m1, qk0, qk1;
            unpack2(m, m0, m1);
            unpack2(Q, qk0, qk1);
            float r0 = fmaxf(-m0, 0.0f);   // max(1-d, 0)
            float r1 = fmaxf(-m1, 0.0f);
            s0 = fmaf(r0, qk0, s0);
            s1 = fmaf(r1, qk1, s1);
        }
        // member corrections: own-cluster term should be attractive d*q, not max(1-d,0)*q
        if ((unsigned)y0 < (unsigned)K) {
            ulonglong2 t0 = s_cxy[y0], t1 = s_czc[y0];
            float cx, cy, cz, c3, qk, hh;
            unpack2(t0.x, cx, hh); unpack2(t0.y, cy, hh);
            unpack2(t1.x, cz, hh); unpack2(t1.y, c3, hh);
            unpack2(s_q[y0], qk, hh);
            float m = fmaf(cx, h0x, fmaf(cy, h0y, fmaf(cz, h0z, c3 + base0)));
            s0 += (m + 1.0f - fmaxf(-m, 0.0f)) * qk;
        }
        if ((unsigned)y1 < (unsigned)K) {
            ulonglong2 t0 = s_cxy[y1], t1 = s_czc[y1];
            float cx, cy, cz, c3, qk, hh;
            unpack2(t0.x, cx, hh); unpack2(t0.y, cy, hh);
            unpack2(t1.x, cz, hh); unpack2(t1.y, c3, hh);
            unpack2(s_q[y1], qk, hh);
            float m = fmaf(cx, h1x, fmaf(cy, h1y, fmaf(cz, h1z, c3 + base1)));
            s1 += (m + 1.0f - fmaxf(-m, 0.0f)) * qk;
        }
        val += s0 * q0 + s1 * q1;
    }

    float bs = blockReduceSum(val);

    // ---------------- finalize + state reset (last block) ----------------
    __shared__ int s_last;
    if (threadIdx.x == 0) {
        atomicAdd(&g_sum_perhit, (double)bs);
        __threadfence();
        unsigned old = atomicAdd(&g_done, 1u);
        s_last = (old == gridDim.x - 1) ? 1 : 0;
    }
    __syncthreads();
    if (s_last) {
        // each thread reads-then-zeros its OWN strided elements (race-free)
        float local = 0.0f;
        for (int k = threadIdx.x; k < K; k += blockDim.x) {
            ull p = __ldcg(&g_pack[k]);
            local += 1.0f - __uint_as_float((unsigned)(p >> 32));
            g_pack[k] = 0ull;
        }
        float sbeta = blockReduceSum(local);
        if (threadIdx.x == 0) {
            float Sb = Sbp ? __ldg(Sbp) : 1.0f;
            double sum_bg = atomicAdd(&g_sum_bg, 0.0);
            double cnt_bg = atomicAdd(&g_cnt_bg, 0.0);
            double sum_ph = atomicAdd(&g_sum_perhit, 0.0);
            if (cnt_bg < 1.0) cnt_bg = 1.0;
            double L = (double)sbeta / (double)K
                     + ((double)Sb / cnt_bg) * sum_bg
                     + sum_ph / (double)N;
            out[0] = (float)L;
            // restore zero-state invariant for next graph replay
            g_sum_bg = 0.0; g_cnt_bg = 0.0; g_sum_perhit = 0.0;
            g_bar_cnt = 0u; g_done = 0u;
        }
        __threadfence();
    }
}

// ================= generic-D fallback (multi-launch) =================
__global__ void k_init() {
    int k = blockIdx.x * blockDim.x + threadIdx.x;
    if (k < KMAX) g_pack[k] = 0ull;
    if (k == 0) { g_sum_bg = 0.0; g_cnt_bg = 0.0; g_sum_perhit = 0.0; g_bar_cnt = 0u; g_done = 0u; }
}

__global__ void k_scan(const float* __restrict__ beta, const int* __restrict__ y, int N) {
    __shared__ ull sh[KMAX];
    for (int k = threadIdx.x; k < KMAX; k += blockDim.x) sh[k] = 0ull;
    __syncthreads();
    float bg = 0.0f, cnt = 0.0f;
    int stride = gridDim.x * blockDim.x;
    for (int i = blockIdx.x * blockDim.x + threadIdx.x; i < N; i += stride) {
        int   yi = y[i];
        float b  = beta[i];
        if (yi >= 0) {
            ull p = ((ull)__float_as_uint(b) << 32) | (ull)(0xFFFFFFFFu - (unsigned)i);
            atomicMax(&sh[yi], p);
        } else { bg += b; cnt += 1.0f; }
    }
    __syncthreads();
    for (int k = threadIdx.x; k < KMAX; k += blockDim.x) {
        ull p = sh[k];
        if (p) atomicMax(&g_pack[k], p);
    }
    float2 r = blockReduceSum2(bg, cnt);
    if (threadIdx.x == 0) {
        if (r.x != 0.0f) atomicAdd(&g_sum_bg, (double)r.x);
        if (r.y != 0.0f) atomicAdd(&g_cnt_bg, (double)r.y);
    }
}

__global__ void k_mainD(const float* __restrict__ x, const float* __restrict__ beta,
                        const int* __restrict__ y, const int* __restrict__ Kp,
                        const float* __restrict__ qminp, int N, int D) {
    extern __shared__ float sm[];
    int   K    = Kp    ? __ldg(Kp)    : 256;
    float qmin = qminp ? __ldg(qminp) : 0.5f;
    float* s_qf = sm;
    float* s_xa = sm + K;
    for (int k = threadIdx.x; k < K; k += blockDim.x) {
        ull p = g_pack[k];
        float q = 0.0f; unsigned idx = 0u;
        if (p != 0ull) {
            float b = __uint_as_float((unsigned)(p >> 32));
            float a = atanhf(b);
            q = fmaf(a, a, qmin);
            idx = 0xFFFFFFFFu - (unsigned)p;
        }
        s_qf[k] = q;
        for (int d = 0; d < D; ++d) s_xa[k * D + d] = x[(size_t)idx * D + d];
    }
    __syncthreads();
    int i = blockIdx.x * blockDim.x + threadIdx.x;
    float val = 0.0f;
    if (i < N) {
        int   yi = y[i];
        float b = beta[i], a = atanhf(b);
        float qi = fmaf(a, a, qmin);
        float acc = 0.0f;
        for (int k = 0; k < K; ++k) {
            float d = 0.0f;
            for (int dd = 0; dd < D; ++dd) {
                float t = x[(size_t)i * D + dd] - s_xa[k * D + dd];
                d = fmaf(t, t, d);
            }
            float t = (k == yi) ? d : fmaxf(1.0f - d, 0.0f);
            acc = fmaf(t, s_qf[k], acc);
        }
        val = acc * qi;
    }
    float bs = blockReduceSum(val);
    if (threadIdx.x == 0) atomicAdd(&g_sum_perhit, (double)bs);
}

__global__ void k_final(const int* __restrict__ Kp, const float* __restrict__ Sbp,
                        float* __restrict__ out, int N) {
    int   K  = Kp  ? __ldg(Kp)  : 256;
    float Sb = Sbp ? __ldg(Sbp) : 1.0f;
    float local = 0.0f;
    for (int k = threadIdx.x; k < K; k += blockDim.x) {
        ull p = g_pack[k];
        local += 1.0f - __uint_as_float((unsigned)(p >> 32));
    }
    float s = blockReduceSum(local);
    if (threadIdx.x == 0) {
        double Nb = g_cnt_bg;
        if (Nb < 1.0) Nb = 1.0;
        double L = (double)s / (double)K
                 + ((double)Sb / Nb) * g_sum_bg
                 + g_sum_perhit / (double)N;
        out[0] = (float)L;
    }
}

extern "C" void kernel_launch(void* const* d_in, const int* in_sizes, int n_in,
                              void* d_out, int out_size) {
    const float* x    = (const float*)d_in[0];
    const float* beta = (const float*)d_in[1];
    const int*   y    = (const int*)d_in[2];
    const int*   Kp   = (n_in > 3) ? (const int*)d_in[3]   : nullptr;
    const float* Sbp  = (n_in > 4) ? (const float*)d_in[4] : nullptr;
    const float* qmp  = (n_in > 5) ? (const float*)d_in[5] : nullptr;

    int N = in_sizes[1];
    int D = (N > 0) ? (in_sizes[0] / N) : 3;
    float* out = (float*)d_out;

    if (D == 3) {
        k_fused3<<<NBLK, TB_MAIN>>>(x, beta, y, Kp, Sbp, qmp, out, N);
    } else {
        k_init<<<(KMAX + 255) / 256, 256>>>();
        k_scan<<<NBLK, 256>>>(beta, y, N);
        int blocks = (N + 255) / 256;
        size_t smem = (size_t)KMAX * (1 + (size_t)D) * sizeof(float);
        k_mainD<<<blocks, 256, smem>>>(x, beta, y, Kp, qmp, N, D);
        k_final<<<1, 256>>>(Kp, Sbp, out, N);
        // restore zero-state invariant for the fused path's assumptions
        k_init<<<(KMAX + 255) / 256, 256>>>();
    }
    (void)out_size;
}